// round 15
// baseline (speedup 1.0000x reference)
#include <cuda_runtime.h>
#include <cstdint>

// TropicalLinear forward on GB300:
//   out[n,o] = max_i( x[n,i] + w[o,i] ) + bias[o]
//
// R14: single-wave + balanced-crossbar version of the intra-warp k-split.
//   - warp tile 4n x 4o (acc=16 regs): crossbar 2.0 B/pair, regs ~55-60
//     -> __launch_bounds__(256,4) REALLY gives occ 4.
//   - each CTA runs TWO sequential o-passes (16 o each) -> grid 512 CTAs
//     = exactly one wave at occ 4 (512 <= 592 resident slots). No wave tail.
//   - KC=256 stages (4 per pass) -> half the __syncthreads of KC=128.
//   - natural row-major smem (24 KB static), bank-clean LDS.128 everywhere,
//     butterfly shfl-max epilogue per pass. No scratch, no grid barrier.

#define N_ROWS  128
#define IN_DIM  1024
#define OUT_DIM 1024
#define KC      256                 // k per smem stage
#define NSTAGE  (IN_DIM / KC)       // 4
#define TN      8                   // CTA n-tile
#define TOP     16                  // o-tile per pass
#define NPASS   2                   // CTA covers 32 o total

__device__ __forceinline__ float neg_inf() { return __int_as_float(0xff800000); }

__device__ __forceinline__ unsigned long long add2(unsigned long long a,
                                                   unsigned long long b) {
    unsigned long long r;
    asm("add.rn.f32x2 %0, %1, %2;" : "=l"(r) : "l"(a), "l"(b));
    return r;
}
__device__ __forceinline__ float lo32(unsigned long long v) {
    return __uint_as_float((unsigned int)v);
}
__device__ __forceinline__ float hi32(unsigned long long v) {
    return __uint_as_float((unsigned int)(v >> 32));
}

extern "C" __global__ void __launch_bounds__(256, 4)
tropical_kernel(const float* __restrict__ x,
                const float* __restrict__ w,
                const float* __restrict__ bias,
                float* __restrict__ out)
{
    // natural row-major tiles, float4 granular: 8 KB + 16 KB = 24 KB static
    __shared__ float4 xs4[TN  * (KC / 4)];   // [ 8 rows][64 float4]
    __shared__ float4 ws4[TOP * (KC / 4)];   // [16 rows][64 float4]

    const int tid  = threadIdx.x;
    const int lane = tid & 31;
    const int wid  = tid >> 5;          // 0..7
    const int wn   = wid >> 2;          // 0..1 -> n rows {4wn .. 4wn+3}
    const int wo   = wid & 3;           // 0..3 -> o rows {4wo .. 4wo+3}

    const int o0 = blockIdx.x * (TOP * NPASS);  // 32 o-tiles of 32
    const int n0 = blockIdx.y * TN;             // 16 n-tiles

#pragma unroll 1
    for (int p = 0; p < NPASS; ++p) {
        const int obase = o0 + p * TOP;

        float acc[4][4];
#pragma unroll
        for (int i = 0; i < 4; ++i)
#pragma unroll
            for (int j = 0; j < 4; ++j)
                acc[i][j] = neg_inf();

#pragma unroll 1
        for (int s = 0; s < NSTAGE; ++s) {
            const int k0 = s * KC;

            // ---- stage (coalesced LDG.128 -> linear STS.128, clean) ----
            // x: 8 rows x 64 float4 = 512 -> 2 per thread
#pragma unroll
            for (int it = 0; it < 2; ++it) {
                const int idx = tid + it * 256;
                const int r = idx >> 6, c = idx & 63;
                xs4[idx] = *(const float4*)(x + (size_t)(n0 + r) * IN_DIM + k0 + c * 4);
            }
            // w: 16 rows x 64 float4 = 1024 -> 4 per thread
#pragma unroll
            for (int it = 0; it < 4; ++it) {
                const int idx = tid + it * 256;
                const int r = idx >> 6, c = idx & 63;
                ws4[idx] = *(const float4*)(w + (size_t)(obase + r) * IN_DIM + k0 + c * 4);
            }
            __syncthreads();

            // ---- compute: lane owns k-quads {c*128 + 4*lane} for c=0,1 ----
            // all LDS.128 lane-stride 16B -> bank-clean
#pragma unroll
            for (int c = 0; c < 2; ++c) {
                const int col = c * 32 + lane;
                ulonglong2 xv[4], wv[4];
#pragma unroll
                for (int i = 0; i < 4; ++i)
                    xv[i] = *(const ulonglong2*)&xs4[(4 * wn + i) * 64 + col];
#pragma unroll
                for (int j = 0; j < 4; ++j)
                    wv[j] = *(const ulonglong2*)&ws4[(4 * wo + j) * 64 + col];
#pragma unroll
                for (int i = 0; i < 4; ++i) {
#pragma unroll
                    for (int j = 0; j < 4; ++j) {
                        unsigned long long s0 = add2(xv[i].x, wv[j].x);
                        unsigned long long s1 = add2(xv[i].y, wv[j].y);
                        float t0 = fmaxf(lo32(s0), hi32(s0));
                        float t1 = fmaxf(lo32(s1), hi32(s1));
                        acc[i][j] = fmaxf(acc[i][j], fmaxf(t0, t1));
                    }
                }
            }
            __syncthreads();
        }

        // ---- butterfly shfl-max across lanes (k-slices) ----
#pragma unroll
        for (int i = 0; i < 4; ++i)
#pragma unroll
            for (int j = 0; j < 4; ++j) {
#pragma unroll
                for (int m = 16; m >= 1; m >>= 1)
                    acc[i][j] = fmaxf(acc[i][j],
                                      __shfl_xor_sync(0xffffffffu, acc[i][j], m));
            }

        // ---- write: lanes 0..15 each emit one (i,j) output ----
        const int li = lane >> 2;           // 0..3
        const int lj = lane & 3;            // 0..3
        float v = neg_inf();
#pragma unroll
        for (int i = 0; i < 4; ++i)
#pragma unroll
            for (int j = 0; j < 4; ++j)
                if (li == i && lj == j) v = acc[i][j];

        if (lane < 16) {
            const int n = n0 + 4 * wn + li;
            const int o = obase + 4 * wo + lj;
            out[(size_t)n * OUT_DIM + o] = v + __ldg(&bias[o]);
        }
    }
}

extern "C" void kernel_launch(void* const* d_in, const int* in_sizes, int n_in,
                              void* d_out, int out_size)
{
    const float* x    = (const float*)d_in[0];   // [128, 1024]
    const float* w    = (const float*)d_in[1];   // [1024, 1024]
    const float* bias = (const float*)d_in[2];   // [1024]
    float* out = (float*)d_out;                  // [128, 1024]

    dim3 grid(OUT_DIM / (TOP * NPASS), N_ROWS / TN);   // (32, 16) = 512 CTAs
    tropical_kernel<<<grid, 256>>>(x, w, bias, out);
}

// round 16
// speedup vs baseline: 1.1597x; 1.1597x over previous
#include <cuda_runtime.h>
#include <cstdint>

// TropicalLinear forward on GB300:
//   out[n,o] = max_i( x[n,i] + w[o,i] ) + bias[o]
//
// R15: broadcast-x k-major core (cheapest crossbar: ~1.06 B/pair) +
//      double-buffered smem pipeline (LDG prefetch overlaps compute) +
//      single-wave grid.
//   - 256-thr CTA, 8 warps; warp tile 4n x 128o (lane o = 4*lane..+3)
//   - per k: 2 bcast LDS.128 (dup x) + 1 LDS.128 (w) + 8 ADD2 + 16 FMNMX
//   - strides: x-dup 68 (16B-aligned bcast all k), w 132 (aligned, bank-clean)
//   - SPLIT=16 -> 512 CTAs = one wave @ occ 4 (__launch_bounds__(256,4))
//   - ticket spin barrier + fused combine (16 partials + bias)

#define N_ROWS  128
#define IN_DIM  1024
#define OUT_DIM 1024
#define SPLIT   16
#define KC      (IN_DIM / SPLIT)   // 64 k per CTA
#define KS      32                 // k per smem stage (2 stages, 2 buffers)
#define TN      32                 // CTA n-tile
#define TO      128                // CTA o-tile
#define NCTA    512
#define XSTR    68                 // x-dup row stride (floats): 272B, 16B-mult
#define WSTR    132                // w row stride (floats): 528B, 16B-mult

#define XBUF_FL (KS * XSTR)        // 2176 floats
#define WBUF_FL (KS * WSTR)        // 4224 floats
#define BUF_FL  (XBUF_FL + WBUF_FL)

// 16 * 128 * 1024 floats = 8 MB static scratch (allocation-free rule)
__device__ float        g_part[SPLIT * N_ROWS * OUT_DIM];
__device__ unsigned int g_arrive;   // zero-init; monotonic across replays

__device__ __forceinline__ float neg_inf() { return __int_as_float(0xff800000); }

__device__ __forceinline__ unsigned long long add2(unsigned long long a,
                                                   unsigned long long b) {
    unsigned long long r;
    asm("add.rn.f32x2 %0, %1, %2;" : "=l"(r) : "l"(a), "l"(b));
    return r;
}
__device__ __forceinline__ float lo32(unsigned long long v) {
    return __uint_as_float((unsigned int)v);
}
__device__ __forceinline__ float hi32(unsigned long long v) {
    return __uint_as_float((unsigned int)(v >> 32));
}

extern "C" __global__ void __launch_bounds__(256, 4)
tropical_fused_kernel(const float* __restrict__ x,
                      const float* __restrict__ w,
                      const float* __restrict__ bias,
                      float* __restrict__ out)
{
    extern __shared__ float smem[];   // 2 * BUF_FL floats = 51200 B

    const int tid  = threadIdx.x;
    const int lane = tid & 31;
    const int wid  = tid >> 5;          // 0..7 -> n rows {4wid .. 4wid+3}

    const int o0 = blockIdx.x * TO;
    const int n0 = blockIdx.y * TN;
    const int k0 = blockIdx.z * KC;
    const int flat_cta = blockIdx.x + blockIdx.y * 8 + blockIdx.z * 32; // 0..511

    // staging coordinates
    const int xrow = tid >> 3;          // 0..31 (n)
    const int xc4  = tid & 7;           // float4 col within 32-k stage
    const int wrow = tid >> 1;          // 0..127 (o)
    const int wq   = tid & 1;           // half of the 32-k stage

    float4 fx;                          // x prefetch: 1 float4 / thread
    float4 fw[4];                       // w prefetch: 4 float4 / thread

    // ---- LDG stage 0 ----
    fx = *(const float4*)(x + (size_t)(n0 + xrow) * IN_DIM + k0 + xc4 * 4);
#pragma unroll
    for (int i = 0; i < 4; ++i)
        fw[i] = *(const float4*)(w + (size_t)(o0 + wrow) * IN_DIM + k0 +
                                 wq * 16 + i * 4);

    float acc[4][4];
#pragma unroll
    for (int i = 0; i < 4; ++i)
#pragma unroll
        for (int j = 0; j < 4; ++j)
            acc[i][j] = neg_inf();

#pragma unroll
    for (int s = 0; s < 2; ++s) {
        float* xs2 = smem + s * BUF_FL;
        float* ws  = xs2 + XBUF_FL;

        // ---- STS current stage (transpose to k-major; x duplicated) ----
        {
            const float xv[4] = {fx.x, fx.y, fx.z, fx.w};
#pragma unroll
            for (int j = 0; j < 4; ++j)
                *(float2*)&xs2[(xc4 * 4 + j) * XSTR + 2 * xrow] =
                    make_float2(xv[j], xv[j]);
#pragma unroll
            for (int i = 0; i < 4; ++i) {
                const int kb = wq * 16 + i * 4;
                ws[(kb + 0) * WSTR + wrow] = fw[i].x;
                ws[(kb + 1) * WSTR + wrow] = fw[i].y;
                ws[(kb + 2) * WSTR + wrow] = fw[i].z;
                ws[(kb + 3) * WSTR + wrow] = fw[i].w;
            }
        }
        __syncthreads();

        // ---- prefetch next stage (overlaps compute below) ----
        if (s == 0) {
            fx = *(const float4*)(x + (size_t)(n0 + xrow) * IN_DIM + k0 + KS +
                                  xc4 * 4);
#pragma unroll
            for (int i = 0; i < 4; ++i)
                fw[i] = *(const float4*)(w + (size_t)(o0 + wrow) * IN_DIM + k0 +
                                         KS + wq * 16 + i * 4);
        }

        // ---- compute: per k = 2 bcast LDS.128 + 1 LDS.128 + 8 ADD2 + 16 FMNMX
        // xs2 reads: all lanes same addr -> broadcast (1 wf)
        // ws read: lanes contiguous float4 -> each 8-lane phase = 32 banks
#pragma unroll 4
        for (int k = 0; k < KS; ++k) {
            const ulonglong2 xa = *(const ulonglong2*)&xs2[k * XSTR + 8 * wid];
            const ulonglong2 xb = *(const ulonglong2*)&xs2[k * XSTR + 8 * wid + 4];
            const ulonglong2 wv = *(const ulonglong2*)&ws[k * WSTR + 4 * lane];
            unsigned long long xd[4] = {xa.x, xa.y, xb.x, xb.y};
#pragma unroll
            for (int i = 0; i < 4; ++i) {
                unsigned long long s0 = add2(xd[i], wv.x);  // o = 4l, 4l+1
                unsigned long long s1 = add2(xd[i], wv.y);  // o = 4l+2, 4l+3
                acc[i][0] = fmaxf(acc[i][0], lo32(s0));
                acc[i][1] = fmaxf(acc[i][1], hi32(s0));
                acc[i][2] = fmaxf(acc[i][2], lo32(s1));
                acc[i][3] = fmaxf(acc[i][3], hi32(s1));
            }
        }
        // no barrier needed before STS of the OTHER buffer (disjoint);
        // the top-of-loop STS is followed by __syncthreads before reads.
        if (s == 0) __syncthreads();   // all warps done with buf0 staging reads
    }

    // ---- write partial maxes (float4, 512 B/warp coalesced) ----
    float* pbase = g_part + (size_t)blockIdx.z * (N_ROWS * OUT_DIM);
#pragma unroll
    for (int i = 0; i < 4; ++i) {
        const int row = n0 + 4 * wid + i;
        float4 a = make_float4(acc[i][0], acc[i][1], acc[i][2], acc[i][3]);
        *(float4*)(pbase + (size_t)row * OUT_DIM + o0 + 4 * lane) = a;
    }

    // ---- grid-wide barrier: monotonic ticket epochs (replay-safe) ----
    __threadfence();
    __syncthreads();
    if (tid == 0) {
        unsigned int ticket = atomicAdd(&g_arrive, 1u) + 1u;
        unsigned int target = ((ticket + NCTA - 1u) / NCTA) * NCTA;
        unsigned int v;
        do {
            asm volatile("ld.acquire.gpu.u32 %0, [%1];"
                         : "=r"(v) : "l"(&g_arrive) : "memory");
        } while (v < target);
    }
    __syncthreads();

    // ---- fused combine: CTAs 0..127 each reduce one output row ----
    if (flat_cta < N_ROWS) {
        const int n  = flat_cta;
        const int o4 = tid * 4;                       // 256 thr x 4 o = 1024
        const float* p = g_part + (size_t)n * OUT_DIM + o4;
        float4 m = make_float4(neg_inf(), neg_inf(), neg_inf(), neg_inf());
#pragma unroll
        for (int s = 0; s < SPLIT; ++s) {
            float4 v = __ldcg((const float4*)(p + (size_t)s * (N_ROWS * OUT_DIM)));
            m.x = fmaxf(m.x, v.x);
            m.y = fmaxf(m.y, v.y);
            m.z = fmaxf(m.z, v.z);
            m.w = fmaxf(m.w, v.w);
        }
        float4 b = *(const float4*)(bias + o4);
        m.x += b.x; m.y += b.y; m.z += b.z; m.w += b.w;
        *(float4*)(out + (size_t)n * OUT_DIM + o4) = m;
    }
}

extern "C" void kernel_launch(void* const* d_in, const int* in_sizes, int n_in,
                              void* d_out, int out_size)
{
    const float* x    = (const float*)d_in[0];   // [128, 1024]
    const float* w    = (const float*)d_in[1];   // [1024, 1024]
    const float* bias = (const float*)d_in[2];   // [1024]
    float* out = (float*)d_out;                  // [128, 1024]

    const int smem_bytes = 2 * BUF_FL * (int)sizeof(float);   // 51200 B
    static bool attr_set = false;
    if (!attr_set) {
        cudaFuncSetAttribute(tropical_fused_kernel,
                             cudaFuncAttributeMaxDynamicSharedMemorySize, smem_bytes);
        attr_set = true;
    }

    dim3 grid(OUT_DIM / TO, N_ROWS / TN, SPLIT);  // (8, 4, 16) = 512 CTAs
    tropical_fused_kernel<<<grid, 256, smem_bytes>>>(x, w, bias, out);
}

// round 17
// speedup vs baseline: 1.4129x; 1.2183x over previous
#include <cuda_runtime.h>
#include <cstdint>

// TropicalLinear forward on GB300:
//   out[n,o] = max_i( x[n,i] + w[o,i] ) + bias[o]
//
// R16: k-pair packed form, NO duplication, NO transpose.
//   - natural row-major smem tiles, stride 68 floats (68 mod 32 = 4):
//       x reads:  warp-broadcast LDS.128 (1 wf)
//       w reads:  lane stride 68 -> every 8-lane phase covers all 32 banks
//   - thread tile 4n x 4o (o = lane + 32j), per k-quad:
//       8 LDS.128 + 32 ADD.F32X2 + 64 FMNMX  = 1.625 slots/pair (session best)
//   - CTA 512 thr: 64n x 128o x 64k, SPLIT=16 -> 256 CTAs = ONE wave @ occ 2
//   - single smem stage (52 KB), one __syncthreads before compute
//   - ticket spin barrier (replay-safe) + fused combine (16 partials + bias)

#define N_ROWS  128
#define IN_DIM  1024
#define OUT_DIM 1024
#define SPLIT   16
#define KC      (IN_DIM / SPLIT)   // 64 k per CTA
#define TN      64
#define TO      128
#define NCTA    256
#define STR     68                 // smem row stride (floats); 68 mod 32 = 4

// 16 * 128 * 1024 floats = 8 MB static scratch (allocation-free rule)
__device__ float        g_part[SPLIT * N_ROWS * OUT_DIM];
__device__ unsigned int g_arrive;   // zero-init; monotonic across replays

__device__ __forceinline__ float neg_inf() { return __int_as_float(0xff800000); }

__device__ __forceinline__ unsigned long long add2(unsigned long long a,
                                                   unsigned long long b) {
    unsigned long long r;
    asm("add.rn.f32x2 %0, %1, %2;" : "=l"(r) : "l"(a), "l"(b));
    return r;
}
__device__ __forceinline__ float lo32(unsigned long long v) {
    return __uint_as_float((unsigned int)v);
}
__device__ __forceinline__ float hi32(unsigned long long v) {
    return __uint_as_float((unsigned int)(v >> 32));
}

extern "C" __global__ void __launch_bounds__(512, 2)
tropical_fused_kernel(const float* __restrict__ x,
                      const float* __restrict__ w,
                      const float* __restrict__ bias,
                      float* __restrict__ out)
{
    // xs: [TN][STR] = 64*68*4  = 17408 B
    // ws: [TO][STR] = 128*68*4 = 34816 B   (52224 B total, dynamic)
    extern __shared__ float smem[];
    float* xs = smem;
    float* ws = smem + TN * STR;

    const int tid  = threadIdx.x;
    const int lane = tid & 31;
    const int wid  = tid >> 5;          // 0..15 -> n rows {4wid .. 4wid+3}

    const int o0 = blockIdx.x * TO;
    const int n0 = blockIdx.y * TN;
    const int k0 = blockIdx.z * KC;
    const int flat_cta = blockIdx.x + blockIdx.y * 8 + blockIdx.z * 16; // 0..255

    // ---- stage tiles: natural row-major, fully coalesced, bank-clean ----
    // w: 128 rows x 16 float4 = 2048 -> 4 per thread
    {
        const int row = tid >> 4;       // 0..31 (+32 per iter)
        const int c4  = tid & 15;
#pragma unroll
        for (int it = 0; it < 4; ++it) {
            const int r = row + it * 32;
            float4 v = *(const float4*)(w + (size_t)(o0 + r) * IN_DIM + k0 + c4 * 4);
            *(float4*)&ws[r * STR + c4 * 4] = v;
        }
        // x: 64 rows x 16 float4 = 1024 -> 2 per thread
#pragma unroll
        for (int it = 0; it < 2; ++it) {
            const int r = row + it * 32;
            float4 v = *(const float4*)(x + (size_t)(n0 + r) * IN_DIM + k0 + c4 * 4);
            *(float4*)&xs[r * STR + c4 * 4] = v;
        }
    }
    __syncthreads();

    float acc[4][4];
#pragma unroll
    for (int i = 0; i < 4; ++i)
#pragma unroll
        for (int j = 0; j < 4; ++j)
            acc[i][j] = neg_inf();

    // ---- compute: per k-quad = 4 bcast LDS + 4 lane LDS + 32 ADD2 + 64 FMNMX
#pragma unroll 2
    for (int kq = 0; kq < KC / 4; ++kq) {
        const int kof = kq * 4;
        ulonglong2 xv[4];
#pragma unroll
        for (int i = 0; i < 4; ++i)
            xv[i] = *(const ulonglong2*)&xs[(4 * wid + i) * STR + kof];
#pragma unroll
        for (int j = 0; j < 4; ++j) {
            const ulonglong2 wv = *(const ulonglong2*)&ws[(lane + 32 * j) * STR + kof];
#pragma unroll
            for (int i = 0; i < 4; ++i) {
                unsigned long long s0 = add2(xv[i].x, wv.x);   // k, k+1
                unsigned long long s1 = add2(xv[i].y, wv.y);   // k+2, k+3
                float t0 = fmaxf(lo32(s0), hi32(s0));
                float t1 = fmaxf(lo32(s1), hi32(s1));
                acc[i][j] = fmaxf(acc[i][j], fmaxf(t0, t1));
            }
        }
    }

    // ---- write partial maxes (per j: 32 lanes x 4B = 128B coalesced) ----
    float* pbase = g_part + (size_t)blockIdx.z * (N_ROWS * OUT_DIM);
#pragma unroll
    for (int i = 0; i < 4; ++i) {
        const int row = n0 + 4 * wid + i;
#pragma unroll
        for (int j = 0; j < 4; ++j)
            pbase[(size_t)row * OUT_DIM + o0 + lane + 32 * j] = acc[i][j];
    }

    // ---- grid-wide barrier: monotonic ticket epochs (replay-safe) ----
    __threadfence();
    __syncthreads();
    if (tid == 0) {
        unsigned int ticket = atomicAdd(&g_arrive, 1u) + 1u;
        unsigned int target = ((ticket + NCTA - 1u) / NCTA) * NCTA;
        unsigned int v;
        do {
            asm volatile("ld.acquire.gpu.u32 %0, [%1];"
                         : "=r"(v) : "l"(&g_arrive) : "memory");
        } while (v < target);
    }
    __syncthreads();

    // ---- fused combine: CTAs 0..127 each reduce one output row ----
    if (flat_cta < N_ROWS && tid < 256) {
        const int n  = flat_cta;
        const int o4 = tid * 4;                       // 256 thr x 4 o = 1024
        const float* p = g_part + (size_t)n * OUT_DIM + o4;
        float4 m = make_float4(neg_inf(), neg_inf(), neg_inf(), neg_inf());
#pragma unroll
        for (int s = 0; s < SPLIT; ++s) {
            float4 v = __ldcg((const float4*)(p + (size_t)s * (N_ROWS * OUT_DIM)));
            m.x = fmaxf(m.x, v.x);
            m.y = fmaxf(m.y, v.y);
            m.z = fmaxf(m.z, v.z);
            m.w = fmaxf(m.w, v.w);
        }
        float4 b = *(const float4*)(bias + o4);
        m.x += b.x; m.y += b.y; m.z += b.z; m.w += b.w;
        *(float4*)(out + (size_t)n * OUT_DIM + o4) = m;
    }
}

extern "C" void kernel_launch(void* const* d_in, const int* in_sizes, int n_in,
                              void* d_out, int out_size)
{
    const float* x    = (const float*)d_in[0];   // [128, 1024]
    const float* w    = (const float*)d_in[1];   // [1024, 1024]
    const float* bias = (const float*)d_in[2];   // [1024]
    float* out = (float*)d_out;                  // [128, 1024]

    const int smem_bytes = (TN + TO) * STR * (int)sizeof(float);  // 52224 B
    static bool attr_set = false;
    if (!attr_set) {
        cudaFuncSetAttribute(tropical_fused_kernel,
                             cudaFuncAttributeMaxDynamicSharedMemorySize, smem_bytes);
        attr_set = true;
    }

    dim3 grid(OUT_DIM / TO, N_ROWS / TN, SPLIT);  // (8, 2, 16) = 256 CTAs
    tropical_fused_kernel<<<grid, 512, smem_bytes>>>(x, w, bias, out);
}